// round 1
// baseline (speedup 1.0000x reference)
#include <cuda_runtime.h>
#include <math.h>

// Problem constants
#define DIMC   768
#define NHEADS 12
#define HDIM   64
#define BATCH  8
#define SEQ    1024
#define MROWS  (BATCH*SEQ)        // 8192
#define PAIRS  (BATCH*NHEADS)     // 96
#define ATT_SCALE 0.125f          // 64^-0.5

// ---------------- scratch (static device memory; no cudaMalloc allowed) ----
__device__ __align__(16) float g_Q[(size_t)PAIRS*SEQ*HDIM];
__device__ __align__(16) float g_K[(size_t)PAIRS*SEQ*HDIM];
__device__ __align__(16) float g_V[(size_t)PAIRS*SEQ*HDIM];
__device__ __align__(16) float g_S[(size_t)PAIRS*SEQ*SEQ];   // 402 MB scores
__device__ __align__(16) float g_O[(size_t)MROWS*DIMC];      // attn output (b,n,h*64+d)

// ============================================================================
// Kernel 1: QKV projection.  C[m,n] = sum_k X[m,k]*Wqkv[n,k]   (NT GEMM)
// M=8192, N=2304, K=768. Epilogue scatters into g_Q/g_K/g_V with layout
// [pair = b*12+h][n][d].
// ============================================================================
__global__ __launch_bounds__(256) void qkv_gemm(const float* __restrict__ A,
                                                const float* __restrict__ W) {
    const int K = DIMC;
    __shared__ float As[8][132];
    __shared__ float Bs[8][132];
    int tid  = threadIdx.x;
    int brow = blockIdx.y * 128;
    int bcol = blockIdx.x * 128;
    int lr = tid >> 1;
    int lk = (tid & 1) * 4;
    int ty = tid >> 4;
    int tx = tid & 15;
    const float* Ap = A + (size_t)(brow + lr) * K + lk;
    const float* Bp = W + (size_t)(bcol + lr) * K + lk;

    float acc[8][8];
#pragma unroll
    for (int i = 0; i < 8; i++)
#pragma unroll
        for (int j = 0; j < 8; j++) acc[i][j] = 0.f;

    for (int k0 = 0; k0 < K; k0 += 8) {
        float4 a4 = *reinterpret_cast<const float4*>(Ap + k0);
        float4 b4 = *reinterpret_cast<const float4*>(Bp + k0);
        As[lk+0][lr] = a4.x; As[lk+1][lr] = a4.y; As[lk+2][lr] = a4.z; As[lk+3][lr] = a4.w;
        Bs[lk+0][lr] = b4.x; Bs[lk+1][lr] = b4.y; Bs[lk+2][lr] = b4.z; Bs[lk+3][lr] = b4.w;
        __syncthreads();
#pragma unroll
        for (int kk = 0; kk < 8; kk++) {
            float af[8], bf[8];
            float4 t0 = *reinterpret_cast<const float4*>(&As[kk][ty*8]);
            float4 t1 = *reinterpret_cast<const float4*>(&As[kk][ty*8+4]);
            float4 u0 = *reinterpret_cast<const float4*>(&Bs[kk][tx*8]);
            float4 u1 = *reinterpret_cast<const float4*>(&Bs[kk][tx*8+4]);
            af[0]=t0.x; af[1]=t0.y; af[2]=t0.z; af[3]=t0.w;
            af[4]=t1.x; af[5]=t1.y; af[6]=t1.z; af[7]=t1.w;
            bf[0]=u0.x; bf[1]=u0.y; bf[2]=u0.z; bf[3]=u0.w;
            bf[4]=u1.x; bf[5]=u1.y; bf[6]=u1.z; bf[7]=u1.w;
#pragma unroll
            for (int i = 0; i < 8; i++)
#pragma unroll
                for (int j = 0; j < 8; j++) acc[i][j] += af[i]*bf[j];
        }
        __syncthreads();
    }

#pragma unroll
    for (int i = 0; i < 8; i++) {
        int row = brow + ty*8 + i;
        int b   = row >> 10;
        int nq  = row & 1023;
#pragma unroll
        for (int j = 0; j < 8; j++) {
            int col  = bcol + tx*8 + j;
            int part = col / 768;
            int rem  = col - part*768;
            int h    = rem >> 6;
            int d    = rem & 63;
            float* dst = (part == 0) ? g_Q : (part == 1) ? g_K : g_V;
            dst[(((size_t)(b*NHEADS + h))*SEQ + nq)*HDIM + d] = acc[i][j];
        }
    }
}

// ============================================================================
// Kernel 2: scores  S = (Q K^T) * SCALE * sigmoid(mask[h])   (NT GEMM, K=64)
// per pair: M=N=1024.
// ============================================================================
__global__ __launch_bounds__(256) void scores_gemm(const float* __restrict__ mask) {
    const int K = HDIM;
    int pair = blockIdx.z;
    int h    = pair % NHEADS;
    const float* A  = g_Q + (size_t)pair * SEQ * HDIM;
    const float* Bk = g_K + (size_t)pair * SEQ * HDIM;
    float*       S  = g_S + (size_t)pair * SEQ * SEQ;

    __shared__ float As[8][132];
    __shared__ float Bs[8][132];
    int tid  = threadIdx.x;
    int brow = blockIdx.y * 128;
    int bcol = blockIdx.x * 128;
    int lr = tid >> 1;
    int lk = (tid & 1) * 4;
    int ty = tid >> 4;
    int tx = tid & 15;
    const float* Ap = A  + (size_t)(brow + lr) * K + lk;
    const float* Bp = Bk + (size_t)(bcol + lr) * K + lk;

    float acc[8][8];
#pragma unroll
    for (int i = 0; i < 8; i++)
#pragma unroll
        for (int j = 0; j < 8; j++) acc[i][j] = 0.f;

    for (int k0 = 0; k0 < K; k0 += 8) {
        float4 a4 = *reinterpret_cast<const float4*>(Ap + k0);
        float4 b4 = *reinterpret_cast<const float4*>(Bp + k0);
        As[lk+0][lr] = a4.x; As[lk+1][lr] = a4.y; As[lk+2][lr] = a4.z; As[lk+3][lr] = a4.w;
        Bs[lk+0][lr] = b4.x; Bs[lk+1][lr] = b4.y; Bs[lk+2][lr] = b4.z; Bs[lk+3][lr] = b4.w;
        __syncthreads();
#pragma unroll
        for (int kk = 0; kk < 8; kk++) {
            float af[8], bf[8];
            float4 t0 = *reinterpret_cast<const float4*>(&As[kk][ty*8]);
            float4 t1 = *reinterpret_cast<const float4*>(&As[kk][ty*8+4]);
            float4 u0 = *reinterpret_cast<const float4*>(&Bs[kk][tx*8]);
            float4 u1 = *reinterpret_cast<const float4*>(&Bs[kk][tx*8+4]);
            af[0]=t0.x; af[1]=t0.y; af[2]=t0.z; af[3]=t0.w;
            af[4]=t1.x; af[5]=t1.y; af[6]=t1.z; af[7]=t1.w;
            bf[0]=u0.x; bf[1]=u0.y; bf[2]=u0.z; bf[3]=u0.w;
            bf[4]=u1.x; bf[5]=u1.y; bf[6]=u1.z; bf[7]=u1.w;
#pragma unroll
            for (int i = 0; i < 8; i++)
#pragma unroll
                for (int j = 0; j < 8; j++) acc[i][j] += af[i]*bf[j];
        }
        __syncthreads();
    }

#pragma unroll
    for (int i = 0; i < 8; i++) {
        int row = brow + ty*8 + i;
        const float* mrow = mask + ((size_t)h*SEQ + row)*SEQ;
#pragma unroll
        for (int j = 0; j < 8; j++) {
            int col = bcol + tx*8 + j;
            float mv = mrow[col];
            float sg = 1.f / (1.f + __expf(-mv));
            S[(size_t)row*SEQ + col] = acc[i][j] * (ATT_SCALE * sg);
        }
    }
}

// ============================================================================
// Kernel 3: row softmax over g_S (98304 rows of 1024)
// ============================================================================
__global__ __launch_bounds__(256) void softmax_rows() {
    __shared__ float red_max[8];
    __shared__ float red_sum[8];
    size_t row = blockIdx.x;
    float* p = g_S + row * (size_t)SEQ;
    int t = threadIdx.x;

    float4 v = reinterpret_cast<float4*>(p)[t];
    float m = fmaxf(fmaxf(v.x, v.y), fmaxf(v.z, v.w));
#pragma unroll
    for (int o = 16; o > 0; o >>= 1) m = fmaxf(m, __shfl_xor_sync(0xffffffffu, m, o));
    if ((t & 31) == 0) red_max[t >> 5] = m;
    __syncthreads();
    if (t == 0) {
        float mm = red_max[0];
#pragma unroll
        for (int i = 1; i < 8; i++) mm = fmaxf(mm, red_max[i]);
        red_max[0] = mm;
    }
    __syncthreads();
    float bm = red_max[0];

    v.x = __expf(v.x - bm);
    v.y = __expf(v.y - bm);
    v.z = __expf(v.z - bm);
    v.w = __expf(v.w - bm);
    float s = v.x + v.y + v.z + v.w;
#pragma unroll
    for (int o = 16; o > 0; o >>= 1) s += __shfl_xor_sync(0xffffffffu, s, o);
    if ((t & 31) == 0) red_sum[t >> 5] = s;
    __syncthreads();
    if (t == 0) {
        float ss = red_sum[0];
#pragma unroll
        for (int i = 1; i < 8; i++) ss += red_sum[i];
        red_sum[0] = ss;
    }
    __syncthreads();
    float inv = 1.f / red_sum[0];

    v.x *= inv; v.y *= inv; v.z *= inv; v.w *= inv;
    reinterpret_cast<float4*>(p)[t] = v;
}

// ============================================================================
// Kernel 4: O = P @ V   (NN GEMM)  per pair: M=1024, N=64, K=1024.
// Epilogue writes transposed layout g_O[b*1024+n][h*64+d].
// ============================================================================
__global__ __launch_bounds__(256) void pv_gemm() {
    int pair = blockIdx.z;
    int b = pair / NHEADS, h = pair % NHEADS;
    const float* A  = g_S + (size_t)pair * SEQ * SEQ;   // [1024,1024]
    const float* Vv = g_V + (size_t)pair * SEQ * HDIM;  // [1024,64]

    __shared__ float As[8][132];
    __shared__ float Bs[8][64];
    int tid  = threadIdx.x;
    int brow = blockIdx.y * 128;
    int lr = tid >> 1;
    int lk = (tid & 1) * 4;
    int ty = tid >> 4;      // 0..15 -> rows
    int tx = tid & 15;      // 0..15 -> cols (x4)
    int br = tid >> 5;      // 0..7
    int bc = (tid & 31) * 2;

    const float* Ap = A + (size_t)(brow + lr) * SEQ + lk;

    float acc[8][4];
#pragma unroll
    for (int i = 0; i < 8; i++)
#pragma unroll
        for (int j = 0; j < 4; j++) acc[i][j] = 0.f;

    for (int k0 = 0; k0 < SEQ; k0 += 8) {
        float4 a4 = *reinterpret_cast<const float4*>(Ap + k0);
        As[lk+0][lr] = a4.x; As[lk+1][lr] = a4.y; As[lk+2][lr] = a4.z; As[lk+3][lr] = a4.w;
        float2 b2 = *reinterpret_cast<const float2*>(Vv + (size_t)(k0 + br)*HDIM + bc);
        Bs[br][bc]   = b2.x;
        Bs[br][bc+1] = b2.y;
        __syncthreads();
#pragma unroll
        for (int kk = 0; kk < 8; kk++) {
            float af[8], bf[4];
            float4 t0 = *reinterpret_cast<const float4*>(&As[kk][ty*8]);
            float4 t1 = *reinterpret_cast<const float4*>(&As[kk][ty*8+4]);
            float4 u  = *reinterpret_cast<const float4*>(&Bs[kk][tx*4]);
            af[0]=t0.x; af[1]=t0.y; af[2]=t0.z; af[3]=t0.w;
            af[4]=t1.x; af[5]=t1.y; af[6]=t1.z; af[7]=t1.w;
            bf[0]=u.x; bf[1]=u.y; bf[2]=u.z; bf[3]=u.w;
#pragma unroll
            for (int i = 0; i < 8; i++)
#pragma unroll
                for (int j = 0; j < 4; j++) acc[i][j] += af[i]*bf[j];
        }
        __syncthreads();
    }

#pragma unroll
    for (int i = 0; i < 8; i++) {
        int row = brow + ty*8 + i;   // query index within pair
        float* orow = g_O + ((size_t)b*SEQ + row)*DIMC + h*HDIM;
#pragma unroll
        for (int j = 0; j < 4; j++) {
            orow[tx*4 + j] = acc[i][j];
        }
    }
}

// ============================================================================
// Kernel 5: output projection.  out = O @ Wproj^T + bias   (NT GEMM)
// M=8192, N=768, K=768.
// ============================================================================
__global__ __launch_bounds__(256) void proj_gemm(const float* __restrict__ W,
                                                 const float* __restrict__ bias,
                                                 float* __restrict__ out) {
    const int K = DIMC;
    __shared__ float As[8][132];
    __shared__ float Bs[8][132];
    int tid  = threadIdx.x;
    int brow = blockIdx.y * 128;
    int bcol = blockIdx.x * 128;
    int lr = tid >> 1;
    int lk = (tid & 1) * 4;
    int ty = tid >> 4;
    int tx = tid & 15;
    const float* Ap = g_O + (size_t)(brow + lr) * K + lk;
    const float* Bp = W   + (size_t)(bcol + lr) * K + lk;

    float acc[8][8];
#pragma unroll
    for (int i = 0; i < 8; i++)
#pragma unroll
        for (int j = 0; j < 8; j++) acc[i][j] = 0.f;

    for (int k0 = 0; k0 < K; k0 += 8) {
        float4 a4 = *reinterpret_cast<const float4*>(Ap + k0);
        float4 b4 = *reinterpret_cast<const float4*>(Bp + k0);
        As[lk+0][lr] = a4.x; As[lk+1][lr] = a4.y; As[lk+2][lr] = a4.z; As[lk+3][lr] = a4.w;
        Bs[lk+0][lr] = b4.x; Bs[lk+1][lr] = b4.y; Bs[lk+2][lr] = b4.z; Bs[lk+3][lr] = b4.w;
        __syncthreads();
#pragma unroll
        for (int kk = 0; kk < 8; kk++) {
            float af[8], bf[8];
            float4 t0 = *reinterpret_cast<const float4*>(&As[kk][ty*8]);
            float4 t1 = *reinterpret_cast<const float4*>(&As[kk][ty*8+4]);
            float4 u0 = *reinterpret_cast<const float4*>(&Bs[kk][tx*8]);
            float4 u1 = *reinterpret_cast<const float4*>(&Bs[kk][tx*8+4]);
            af[0]=t0.x; af[1]=t0.y; af[2]=t0.z; af[3]=t0.w;
            af[4]=t1.x; af[5]=t1.y; af[6]=t1.z; af[7]=t1.w;
            bf[0]=u0.x; bf[1]=u0.y; bf[2]=u0.z; bf[3]=u0.w;
            bf[4]=u1.x; bf[5]=u1.y; bf[6]=u1.z; bf[7]=u1.w;
#pragma unroll
            for (int i = 0; i < 8; i++)
#pragma unroll
                for (int j = 0; j < 8; j++) acc[i][j] += af[i]*bf[j];
        }
        __syncthreads();
    }

#pragma unroll
    for (int i = 0; i < 8; i++) {
        int row = brow + ty*8 + i;
        float* orow = out + (size_t)row * DIMC;
#pragma unroll
        for (int j = 0; j < 8; j++) {
            int col = bcol + tx*8 + j;
            orow[col] = acc[i][j] + bias[col];
        }
    }
}

// ============================================================================
extern "C" void kernel_launch(void* const* d_in, const int* in_sizes, int n_in,
                              void* d_out, int out_size) {
    (void)in_sizes; (void)n_in; (void)out_size;
    const float* x        = (const float*)d_in[0];
    const float* w_qkv    = (const float*)d_in[1];
    const float* w_proj   = (const float*)d_in[2];
    const float* b_proj   = (const float*)d_in[3];
    const float* att_mask = (const float*)d_in[4];
    float* out = (float*)d_out;

    qkv_gemm   <<<dim3(2304/128, MROWS/128), 256>>>(x, w_qkv);
    scores_gemm<<<dim3(SEQ/128, SEQ/128, PAIRS), 256>>>(att_mask);
    softmax_rows<<<PAIRS*SEQ, 256>>>();
    pv_gemm    <<<dim3(1, SEQ/128, PAIRS), 256>>>();
    proj_gemm  <<<dim3(DIMC/128, MROWS/128), 256>>>(w_proj, b_proj, out);
}

// round 3
// speedup vs baseline: 1.7643x; 1.7643x over previous
#include <cuda_runtime.h>
#include <cstdint>
#include <math.h>

#define DIMC   768
#define NHEADS 12
#define HDIM   64
#define BATCH  8
#define SEQ    1024
#define MROWS  (BATCH*SEQ)
#define PAIRS  (BATCH*NHEADS)
#define ATT_SCALE 0.125f

// ---------------- scratch (static device memory; no cudaMalloc allowed) ----
__device__ __align__(16) float g_Q [(size_t)PAIRS*SEQ*HDIM];
__device__ __align__(16) float g_K [(size_t)PAIRS*SEQ*HDIM];
__device__ __align__(16) float g_Vt[(size_t)PAIRS*HDIM*SEQ];   // [pair][d][n]
__device__ __align__(16) float g_S [(size_t)PAIRS*SEQ*SEQ];    // scores
__device__ __align__(16) float g_O [(size_t)MROWS*DIMC];       // attn out (b,n,h*64+d)

// ======================= helpers ===========================================
__device__ __forceinline__ uint32_t cvt_tf32(float x) {
    uint32_t r; asm("cvt.rna.tf32.f32 %0, %1;" : "=r"(r) : "f"(x)); return r;
}
__device__ __forceinline__ void mma_tf32(float (&c)[4], const uint32_t (&a)[4],
                                         const uint32_t (&b)[2]) {
    asm volatile("mma.sync.aligned.m16n8k8.row.col.f32.tf32.tf32.f32 "
                 "{%0,%1,%2,%3}, {%4,%5,%6,%7}, {%8,%9}, {%0,%1,%2,%3};"
                 : "+f"(c[0]), "+f"(c[1]), "+f"(c[2]), "+f"(c[3])
                 : "r"(a[0]), "r"(a[1]), "r"(a[2]), "r"(a[3]),
                   "r"(b[0]), "r"(b[1]));
}

// ============================================================================
// NT GEMM core: C[128 x BN] = A[128 x K] * B[BN x K]^T, tf32 tensor cores.
// 256 threads = 8 warps. Warp grid: WMDIV x (8/WMDIV). Warp tile (MF*16) x (NF*8).
// K consumed in chunks of 32, register double-buffered LDG.
// Smem LDK=36 padding -> conflict-free fragment loads (bank = 4r+q).
// ============================================================================
template <int BN, int NC, int MF, int NF, int WMDIV>
__device__ __forceinline__ void gemm_core(const float* __restrict__ A, int lda,
                                          const float* __restrict__ B, int ldb,
                                          float (&acc)[MF][NF][4]) {
    constexpr int LDK   = 36;
    constexpr int APASS = 4;        // 128*32 / (256*4)
    constexpr int BPASS = BN / 32;  // BN*32  / (256*4)
    __shared__ float As[128 * LDK];
    __shared__ float Bs[BN * LDK];

    const int tid  = threadIdx.x;
    const int lane = tid & 31;
    const int wid  = tid >> 5;
    const int wm   = wid % WMDIV;
    const int wn   = wid / WMDIV;
    const int mrow0 = wm * (MF * 16);
    const int ncol0 = wn * (NF * 8);
    const int r = lane >> 2, q = lane & 3;

#pragma unroll
    for (int mf = 0; mf < MF; mf++)
#pragma unroll
        for (int nf = 0; nf < NF; nf++)
#pragma unroll
            for (int i = 0; i < 4; i++) acc[mf][nf][i] = 0.f;

    float4 ar[APASS], br[BPASS];
    // prologue: load chunk 0
#pragma unroll
    for (int p = 0; p < APASS; p++) {
        int idx = tid + p * 256;
        ar[p] = *reinterpret_cast<const float4*>(A + (size_t)(idx >> 3) * lda + (idx & 7) * 4);
    }
#pragma unroll
    for (int p = 0; p < BPASS; p++) {
        int idx = tid + p * 256;
        br[p] = *reinterpret_cast<const float4*>(B + (size_t)(idx >> 3) * ldb + (idx & 7) * 4);
    }

#pragma unroll 1
    for (int i = 0; i < NC; i++) {
        // stage current chunk (tf32-rounded) into smem
#pragma unroll
        for (int p = 0; p < APASS; p++) {
            int idx = tid + p * 256;
            uint32_t* d = reinterpret_cast<uint32_t*>(&As[(idx >> 3) * LDK + (idx & 7) * 4]);
            d[0] = cvt_tf32(ar[p].x); d[1] = cvt_tf32(ar[p].y);
            d[2] = cvt_tf32(ar[p].z); d[3] = cvt_tf32(ar[p].w);
        }
#pragma unroll
        for (int p = 0; p < BPASS; p++) {
            int idx = tid + p * 256;
            uint32_t* d = reinterpret_cast<uint32_t*>(&Bs[(idx >> 3) * LDK + (idx & 7) * 4]);
            d[0] = cvt_tf32(br[p].x); d[1] = cvt_tf32(br[p].y);
            d[2] = cvt_tf32(br[p].z); d[3] = cvt_tf32(br[p].w);
        }
        __syncthreads();

        // prefetch next chunk (overlaps with MMA below)
        if (i + 1 < NC) {
            int k0 = (i + 1) * 32;
#pragma unroll
            for (int p = 0; p < APASS; p++) {
                int idx = tid + p * 256;
                ar[p] = *reinterpret_cast<const float4*>(A + (size_t)(idx >> 3) * lda + k0 + (idx & 7) * 4);
            }
#pragma unroll
            for (int p = 0; p < BPASS; p++) {
                int idx = tid + p * 256;
                br[p] = *reinterpret_cast<const float4*>(B + (size_t)(idx >> 3) * ldb + k0 + (idx & 7) * 4);
            }
        }

        // compute this chunk: 4 k-steps of m16n8k8
#pragma unroll
        for (int kk = 0; kk < 32; kk += 8) {
            uint32_t af[MF][4], bf[NF][2];
#pragma unroll
            for (int mf = 0; mf < MF; mf++) {
                const float* ap = &As[(mrow0 + mf * 16 + r) * LDK + kk + q];
                af[mf][0] = __float_as_uint(ap[0]);
                af[mf][1] = __float_as_uint(ap[8 * LDK]);
                af[mf][2] = __float_as_uint(ap[4]);
                af[mf][3] = __float_as_uint(ap[8 * LDK + 4]);
            }
#pragma unroll
            for (int nf = 0; nf < NF; nf++) {
                const float* bp = &Bs[(ncol0 + nf * 8 + r) * LDK + kk + q];
                bf[nf][0] = __float_as_uint(bp[0]);
                bf[nf][1] = __float_as_uint(bp[4]);
            }
#pragma unroll
            for (int mf = 0; mf < MF; mf++)
#pragma unroll
                for (int nf = 0; nf < NF; nf++)
                    mma_tf32(acc[mf][nf], af[mf], bf[nf]);
        }
        __syncthreads();
    }
}

// ============================================================================
// Kernel 1: QKV projection (M=8192, N=2304, K=768) + scatter to Q/K/Vt
// ============================================================================
__global__ __launch_bounds__(256) void qkv_tc(const float* __restrict__ x,
                                              const float* __restrict__ w) {
    float acc[4][4][4];
    int brow = blockIdx.y * 128, bcol = blockIdx.x * 128;
    gemm_core<128, 24, 4, 4, 2>(x + (size_t)brow * DIMC, DIMC,
                                w + (size_t)bcol * DIMC, DIMC, acc);
    int lane = threadIdx.x & 31, wid = threadIdx.x >> 5;
    int wm = wid % 2, wn = wid / 2, r = lane >> 2, q = lane & 3;
    int part = bcol / 768, rem0 = bcol - part * 768;

#pragma unroll
    for (int mf = 0; mf < 4; mf++)
#pragma unroll
        for (int nf = 0; nf < 4; nf++) {
            int col = rem0 + wn * 32 + nf * 8 + q * 2;
            int h = col >> 6, d = col & 63;
#pragma unroll
            for (int rr = 0; rr < 2; rr++) {
                int m = brow + wm * 64 + mf * 16 + r + rr * 8;
                int b = m >> 10, nq = m & 1023;
                float v0 = acc[mf][nf][rr * 2 + 0];
                float v1 = acc[mf][nf][rr * 2 + 1];
                if (part < 2) {
                    float* dst = (part == 0) ? g_Q : g_K;
                    *reinterpret_cast<float2*>(
                        &dst[(((size_t)(b * NHEADS + h)) * SEQ + nq) * HDIM + d]) =
                        make_float2(v0, v1);
                } else {
                    size_t pb = ((size_t)(b * NHEADS + h)) * HDIM;
                    g_Vt[(pb + d)     * SEQ + nq] = v0;
                    g_Vt[(pb + d + 1) * SEQ + nq] = v1;
                }
            }
        }
}

// ============================================================================
// Kernel 2: S = (Q K^T) * SCALE * sigmoid(mask[h])  (per pair, K=64)
// ============================================================================
__global__ __launch_bounds__(256) void scores_tc(const float* __restrict__ mask) {
    float acc[4][4][4];
    int pair = blockIdx.z, h = pair % NHEADS;
    int brow = blockIdx.y * 128, bcol = blockIdx.x * 128;
    gemm_core<128, 2, 4, 4, 2>(g_Q + (size_t)pair * SEQ * HDIM + (size_t)brow * HDIM, HDIM,
                               g_K + (size_t)pair * SEQ * HDIM + (size_t)bcol * HDIM, HDIM, acc);
    float* S = g_S + (size_t)pair * SEQ * SEQ;
    const float* M = mask + (size_t)h * SEQ * SEQ;
    int lane = threadIdx.x & 31, wid = threadIdx.x >> 5;
    int wm = wid % 2, wn = wid / 2, r = lane >> 2, q = lane & 3;

#pragma unroll
    for (int mf = 0; mf < 4; mf++)
#pragma unroll
        for (int nf = 0; nf < 4; nf++) {
            int col = bcol + wn * 32 + nf * 8 + q * 2;
#pragma unroll
            for (int rr = 0; rr < 2; rr++) {
                int row = brow + wm * 64 + mf * 16 + r + rr * 8;
                float2 mv = *reinterpret_cast<const float2*>(&M[(size_t)row * SEQ + col]);
                float s0 = acc[mf][nf][rr * 2 + 0] * (ATT_SCALE / (1.f + __expf(-mv.x)));
                float s1 = acc[mf][nf][rr * 2 + 1] * (ATT_SCALE / (1.f + __expf(-mv.y)));
                *reinterpret_cast<float2*>(&S[(size_t)row * SEQ + col]) = make_float2(s0, s1);
            }
        }
}

// ============================================================================
// Kernel 3: row softmax over g_S (98304 rows of 1024)
// ============================================================================
__global__ __launch_bounds__(256) void softmax_rows() {
    __shared__ float red_max[8];
    __shared__ float red_sum[8];
    size_t row = blockIdx.x;
    float* p = g_S + row * (size_t)SEQ;
    int t = threadIdx.x;

    float4 v = reinterpret_cast<float4*>(p)[t];
    float m = fmaxf(fmaxf(v.x, v.y), fmaxf(v.z, v.w));
#pragma unroll
    for (int o = 16; o > 0; o >>= 1) m = fmaxf(m, __shfl_xor_sync(0xffffffffu, m, o));
    if ((t & 31) == 0) red_max[t >> 5] = m;
    __syncthreads();
    if (t == 0) {
        float mm = red_max[0];
#pragma unroll
        for (int i = 1; i < 8; i++) mm = fmaxf(mm, red_max[i]);
        red_max[0] = mm;
    }
    __syncthreads();
    float bm = red_max[0];

    v.x = __expf(v.x - bm); v.y = __expf(v.y - bm);
    v.z = __expf(v.z - bm); v.w = __expf(v.w - bm);
    float s = v.x + v.y + v.z + v.w;
#pragma unroll
    for (int o = 16; o > 0; o >>= 1) s += __shfl_xor_sync(0xffffffffu, s, o);
    if ((t & 31) == 0) red_sum[t >> 5] = s;
    __syncthreads();
    if (t == 0) {
        float ss = red_sum[0];
#pragma unroll
        for (int i = 1; i < 8; i++) ss += red_sum[i];
        red_sum[0] = ss;
    }
    __syncthreads();
    float inv = 1.f / red_sum[0];
    v.x *= inv; v.y *= inv; v.z *= inv; v.w *= inv;
    reinterpret_cast<float4*>(p)[t] = v;
}

// ============================================================================
// Kernel 4: O = P @ V == P(128xK) * Vt(64xK)^T  (per pair, K=1024)
// ============================================================================
__global__ __launch_bounds__(256) void pv_tc() {
    float acc[2][4][4];
    int pair = blockIdx.z;
    int b = pair / NHEADS, h = pair % NHEADS;
    int brow = blockIdx.y * 128;
    gemm_core<64, 32, 2, 4, 4>(g_S + (size_t)pair * SEQ * SEQ + (size_t)brow * SEQ, SEQ,
                               g_Vt + (size_t)pair * HDIM * SEQ, SEQ, acc);
    int lane = threadIdx.x & 31, wid = threadIdx.x >> 5;
    int wm = wid % 4, wn = wid / 4, r = lane >> 2, q = lane & 3;

#pragma unroll
    for (int mf = 0; mf < 2; mf++)
#pragma unroll
        for (int nf = 0; nf < 4; nf++) {
            int d = wn * 32 + nf * 8 + q * 2;
#pragma unroll
            for (int rr = 0; rr < 2; rr++) {
                int n = brow + wm * 32 + mf * 16 + r + rr * 8;
                float v0 = acc[mf][nf][rr * 2 + 0];
                float v1 = acc[mf][nf][rr * 2 + 1];
                *reinterpret_cast<float2*>(
                    &g_O[((size_t)b * SEQ + n) * DIMC + h * HDIM + d]) = make_float2(v0, v1);
            }
        }
}

// ============================================================================
// Kernel 5: out = O @ Wproj^T + bias  (M=8192, N=768, K=768)
// ============================================================================
__global__ __launch_bounds__(256) void proj_tc(const float* __restrict__ w,
                                               const float* __restrict__ bias,
                                               float* __restrict__ out) {
    float acc[4][4][4];
    int brow = blockIdx.y * 128, bcol = blockIdx.x * 128;
    gemm_core<128, 24, 4, 4, 2>(g_O + (size_t)brow * DIMC, DIMC,
                                w + (size_t)bcol * DIMC, DIMC, acc);
    int lane = threadIdx.x & 31, wid = threadIdx.x >> 5;
    int wm = wid % 2, wn = wid / 2, r = lane >> 2, q = lane & 3;

#pragma unroll
    for (int mf = 0; mf < 4; mf++)
#pragma unroll
        for (int nf = 0; nf < 4; nf++) {
            int col = bcol + wn * 32 + nf * 8 + q * 2;
            float2 bb = *reinterpret_cast<const float2*>(&bias[col]);
#pragma unroll
            for (int rr = 0; rr < 2; rr++) {
                int row = brow + wm * 64 + mf * 16 + r + rr * 8;
                float v0 = acc[mf][nf][rr * 2 + 0] + bb.x;
                float v1 = acc[mf][nf][rr * 2 + 1] + bb.y;
                *reinterpret_cast<float2*>(&out[(size_t)row * DIMC + col]) = make_float2(v0, v1);
            }
        }
}

// ============================================================================
extern "C" void kernel_launch(void* const* d_in, const int* in_sizes, int n_in,
                              void* d_out, int out_size) {
    (void)in_sizes; (void)n_in; (void)out_size;
    const float* x        = (const float*)d_in[0];
    const float* w_qkv    = (const float*)d_in[1];
    const float* w_proj   = (const float*)d_in[2];
    const float* b_proj   = (const float*)d_in[3];
    const float* att_mask = (const float*)d_in[4];
    float* out = (float*)d_out;

    qkv_tc    <<<dim3(2304 / 128, MROWS / 128), 256>>>(x, w_qkv);
    scores_tc <<<dim3(SEQ / 128, SEQ / 128, PAIRS), 256>>>(att_mask);
    softmax_rows<<<PAIRS * SEQ, 256>>>();
    pv_tc     <<<dim3(1, SEQ / 128, PAIRS), 256>>>();
    proj_tc   <<<dim3(DIMC / 128, MROWS / 128), 256>>>(w_proj, b_proj, out);
}

// round 4
// speedup vs baseline: 2.5306x; 1.4343x over previous
#include <cuda_runtime.h>
#include <cstdint>
#include <math.h>

#define DIMC   768
#define NHEADS 12
#define HDIM   64
#define BATCH  8
#define SEQ    1024
#define MROWS  (BATCH*SEQ)
#define PAIRS  (BATCH*NHEADS)
#define ATT_SCALE 0.125f

// ---------------- scratch (static device memory; no cudaMalloc allowed) ----
__device__ __align__(16) float g_Q [(size_t)PAIRS*SEQ*HDIM];
__device__ __align__(16) float g_K [(size_t)PAIRS*SEQ*HDIM];
__device__ __align__(16) float g_Vt[(size_t)PAIRS*HDIM*SEQ];   // [pair][d][n]
__device__ __align__(16) float g_O [(size_t)MROWS*DIMC];       // attn out (b,n,h*64+d)

// ======================= helpers ===========================================
__device__ __forceinline__ uint32_t cvt_tf32(float x) {
    uint32_t r; asm("cvt.rna.tf32.f32 %0, %1;" : "=r"(r) : "f"(x)); return r;
}
__device__ __forceinline__ float tf32f(float x) {
    return __uint_as_float(cvt_tf32(x));
}
__device__ __forceinline__ void mma_tf32(float (&c)[4], const uint32_t (&a)[4],
                                         const uint32_t (&b)[2]) {
    asm volatile("mma.sync.aligned.m16n8k8.row.col.f32.tf32.tf32.f32 "
                 "{%0,%1,%2,%3}, {%4,%5,%6,%7}, {%8,%9}, {%0,%1,%2,%3};"
                 : "+f"(c[0]), "+f"(c[1]), "+f"(c[2]), "+f"(c[3])
                 : "r"(a[0]), "r"(a[1]), "r"(a[2]), "r"(a[3]),
                   "r"(b[0]), "r"(b[1]));
}

// ============================================================================
// NT GEMM core (unchanged from R3): C[128 x BN] = A[128 x K] * B[BN x K]^T
// ============================================================================
template <int BN, int NC, int MF, int NF, int WMDIV>
__device__ __forceinline__ void gemm_core(const float* __restrict__ A, int lda,
                                          const float* __restrict__ B, int ldb,
                                          float (&acc)[MF][NF][4]) {
    constexpr int LDK   = 36;
    constexpr int APASS = 4;
    constexpr int BPASS = BN / 32;
    __shared__ float As[128 * LDK];
    __shared__ float Bs[BN * LDK];

    const int tid  = threadIdx.x;
    const int lane = tid & 31;
    const int wid  = tid >> 5;
    const int wm   = wid % WMDIV;
    const int wn   = wid / WMDIV;
    const int mrow0 = wm * (MF * 16);
    const int ncol0 = wn * (NF * 8);
    const int r = lane >> 2, q = lane & 3;

#pragma unroll
    for (int mf = 0; mf < MF; mf++)
#pragma unroll
        for (int nf = 0; nf < NF; nf++)
#pragma unroll
            for (int i = 0; i < 4; i++) acc[mf][nf][i] = 0.f;

    float4 ar[APASS], br[BPASS];
#pragma unroll
    for (int p = 0; p < APASS; p++) {
        int idx = tid + p * 256;
        ar[p] = *reinterpret_cast<const float4*>(A + (size_t)(idx >> 3) * lda + (idx & 7) * 4);
    }
#pragma unroll
    for (int p = 0; p < BPASS; p++) {
        int idx = tid + p * 256;
        br[p] = *reinterpret_cast<const float4*>(B + (size_t)(idx >> 3) * ldb + (idx & 7) * 4);
    }

#pragma unroll 1
    for (int i = 0; i < NC; i++) {
#pragma unroll
        for (int p = 0; p < APASS; p++) {
            int idx = tid + p * 256;
            uint32_t* d = reinterpret_cast<uint32_t*>(&As[(idx >> 3) * LDK + (idx & 7) * 4]);
            d[0] = cvt_tf32(ar[p].x); d[1] = cvt_tf32(ar[p].y);
            d[2] = cvt_tf32(ar[p].z); d[3] = cvt_tf32(ar[p].w);
        }
#pragma unroll
        for (int p = 0; p < BPASS; p++) {
            int idx = tid + p * 256;
            uint32_t* d = reinterpret_cast<uint32_t*>(&Bs[(idx >> 3) * LDK + (idx & 7) * 4]);
            d[0] = cvt_tf32(br[p].x); d[1] = cvt_tf32(br[p].y);
            d[2] = cvt_tf32(br[p].z); d[3] = cvt_tf32(br[p].w);
        }
        __syncthreads();

        if (i + 1 < NC) {
            int k0 = (i + 1) * 32;
#pragma unroll
            for (int p = 0; p < APASS; p++) {
                int idx = tid + p * 256;
                ar[p] = *reinterpret_cast<const float4*>(A + (size_t)(idx >> 3) * lda + k0 + (idx & 7) * 4);
            }
#pragma unroll
            for (int p = 0; p < BPASS; p++) {
                int idx = tid + p * 256;
                br[p] = *reinterpret_cast<const float4*>(B + (size_t)(idx >> 3) * ldb + k0 + (idx & 7) * 4);
            }
        }

#pragma unroll
        for (int kk = 0; kk < 32; kk += 8) {
            uint32_t af[MF][4], bf[NF][2];
#pragma unroll
            for (int mf = 0; mf < MF; mf++) {
                const float* ap = &As[(mrow0 + mf * 16 + r) * LDK + kk + q];
                af[mf][0] = __float_as_uint(ap[0]);
                af[mf][1] = __float_as_uint(ap[8 * LDK]);
                af[mf][2] = __float_as_uint(ap[4]);
                af[mf][3] = __float_as_uint(ap[8 * LDK + 4]);
            }
#pragma unroll
            for (int nf = 0; nf < NF; nf++) {
                const float* bp = &Bs[(ncol0 + nf * 8 + r) * LDK + kk + q];
                bf[nf][0] = __float_as_uint(bp[0]);
                bf[nf][1] = __float_as_uint(bp[4]);
            }
#pragma unroll
            for (int mf = 0; mf < MF; mf++)
#pragma unroll
                for (int nf = 0; nf < NF; nf++)
                    mma_tf32(acc[mf][nf], af[mf], bf[nf]);
        }
        __syncthreads();
    }
}

// ============================================================================
// Kernel 1: QKV projection (M=8192, N=2304, K=768) + scatter to Q/K/Vt
// ============================================================================
__global__ __launch_bounds__(256) void qkv_tc(const float* __restrict__ x,
                                              const float* __restrict__ w) {
    float acc[4][4][4];
    int brow = blockIdx.y * 128, bcol = blockIdx.x * 128;
    gemm_core<128, 24, 4, 4, 2>(x + (size_t)brow * DIMC, DIMC,
                                w + (size_t)bcol * DIMC, DIMC, acc);
    int lane = threadIdx.x & 31, wid = threadIdx.x >> 5;
    int wm = wid % 2, wn = wid / 2, r = lane >> 2, q = lane & 3;
    int part = bcol / 768, rem0 = bcol - part * 768;

#pragma unroll
    for (int mf = 0; mf < 4; mf++)
#pragma unroll
        for (int nf = 0; nf < 4; nf++) {
            int col = rem0 + wn * 32 + nf * 8 + q * 2;
            int h = col >> 6, d = col & 63;
#pragma unroll
            for (int rr = 0; rr < 2; rr++) {
                int m = brow + wm * 64 + mf * 16 + r + rr * 8;
                int b = m >> 10, nq = m & 1023;
                float v0 = acc[mf][nf][rr * 2 + 0];
                float v1 = acc[mf][nf][rr * 2 + 1];
                if (part < 2) {
                    float* dst = (part == 0) ? g_Q : g_K;
                    *reinterpret_cast<float2*>(
                        &dst[(((size_t)(b * NHEADS + h)) * SEQ + nq) * HDIM + d]) =
                        make_float2(v0, v1);
                } else {
                    size_t pb = ((size_t)(b * NHEADS + h)) * HDIM;
                    g_Vt[(pb + d)     * SEQ + nq] = v0;
                    g_Vt[(pb + d + 1) * SEQ + nq] = v1;
                }
            }
        }
}

// ============================================================================
// Kernel 2: FUSED flash attention per (q-tile, pair):
//   S = QK^T * SCALE * sigmoid(mask); P = online-softmax(S); O = P V
// 256 threads = 8 warps; warp w owns q-rows [16w, 16w+16). Key tile KT=64.
// ============================================================================
#define KT 64
#define LDP 68   // smem stride (floats): bank = 4*row + col (mod 32) -> frag loads conflict-free

__global__ __launch_bounds__(256) void flash_tc(const float* __restrict__ mask) {
    extern __shared__ float sm[];
    float* Ks = sm;                 // [64][LDP]
    float* Vs = sm + 64 * LDP;      // [64][LDP]
    float* Ps = sm + 128 * LDP;     // [128][LDP] (staging for Q, then P tiles)

    const int tid = threadIdx.x, lane = tid & 31, wid = tid >> 5;
    const int r = lane >> 2, q = lane & 3;
    const int pair = blockIdx.y;
    const int h = pair % NHEADS, b = pair / NHEADS;
    const int q0 = blockIdx.x * 128;

    const float* Qg = g_Q  + (size_t)pair * SEQ * HDIM + (size_t)q0 * HDIM;
    const float* Kg = g_K  + (size_t)pair * SEQ * HDIM;
    const float* Vg = g_Vt + (size_t)pair * HDIM * SEQ;
    const float* Mg = mask + (size_t)h * SEQ * SEQ;

    // ---- stage Q tile (128x64) into Ps, tf32-rounded ----
#pragma unroll
    for (int p = 0; p < 8; p++) {
        int idx = tid + p * 256;
        int row = idx >> 4, c = idx & 15;
        float4 v = *reinterpret_cast<const float4*>(Qg + (size_t)row * HDIM + c * 4);
        float* d = &Ps[row * LDP + c * 4];
        d[0] = tf32f(v.x); d[1] = tf32f(v.y); d[2] = tf32f(v.z); d[3] = tf32f(v.w);
    }
    __syncthreads();

    // ---- Q fragments held in registers for the whole kernel ----
    uint32_t qa[8][4];
#pragma unroll
    for (int kk = 0; kk < 8; kk++) {
        const float* ap = &Ps[(wid * 16 + r) * LDP + kk * 8 + q];
        qa[kk][0] = __float_as_uint(ap[0]);
        qa[kk][1] = __float_as_uint(ap[8 * LDP]);
        qa[kk][2] = __float_as_uint(ap[4]);
        qa[kk][3] = __float_as_uint(ap[8 * LDP + 4]);
    }
    __syncthreads();

    float od[8][4];
#pragma unroll
    for (int nf = 0; nf < 8; nf++)
#pragma unroll
        for (int i = 0; i < 4; i++) od[nf][i] = 0.f;
    float m0 = -1e30f, m1 = -1e30f, l0 = 0.f, l1 = 0.f;

    const int row_s0 = q0 + wid * 16 + r;      // global seq row (for mask)

#pragma unroll 1
    for (int kb = 0; kb < SEQ / KT; kb++) {
        // ---- load K tile [64][64] and V tile (Vt) [64 d][64 keys] ----
        const float* Ksrc = Kg + (size_t)kb * KT * HDIM;
#pragma unroll
        for (int p = 0; p < 4; p++) {
            int idx = tid + p * 256;
            int row = idx >> 4, c = idx & 15;
            float4 v = *reinterpret_cast<const float4*>(Ksrc + (size_t)row * HDIM + c * 4);
            float* d = &Ks[row * LDP + c * 4];
            d[0] = tf32f(v.x); d[1] = tf32f(v.y); d[2] = tf32f(v.z); d[3] = tf32f(v.w);
        }
#pragma unroll
        for (int p = 0; p < 4; p++) {
            int idx = tid + p * 256;
            int dd = idx >> 4, c = idx & 15;
            float4 v = *reinterpret_cast<const float4*>(Vg + (size_t)dd * SEQ + kb * KT + c * 4);
            float* d = &Vs[dd * LDP + c * 4];
            d[0] = tf32f(v.x); d[1] = tf32f(v.y); d[2] = tf32f(v.z); d[3] = tf32f(v.w);
        }
        __syncthreads();

        // ---- S = Q K^T for this tile (16 rows x 64 keys per warp) ----
        float sacc[8][4];
#pragma unroll
        for (int nf = 0; nf < 8; nf++)
#pragma unroll
            for (int i = 0; i < 4; i++) sacc[nf][i] = 0.f;
#pragma unroll
        for (int kk = 0; kk < 8; kk++) {
#pragma unroll
            for (int nf = 0; nf < 8; nf++) {
                uint32_t bf[2];
                const float* bp = &Ks[(nf * 8 + r) * LDP + kk * 8 + q];
                bf[0] = __float_as_uint(bp[0]);
                bf[1] = __float_as_uint(bp[4]);
                mma_tf32(sacc[nf], qa[kk], bf);
            }
        }

        // ---- mask * sigmoid, online softmax ----
        float mx0 = -1e30f, mx1 = -1e30f;
#pragma unroll
        for (int nf = 0; nf < 8; nf++) {
            int col = kb * KT + nf * 8 + 2 * q;
            float2 mv0 = *reinterpret_cast<const float2*>(&Mg[(size_t)row_s0 * SEQ + col]);
            float2 mv1 = *reinterpret_cast<const float2*>(&Mg[(size_t)(row_s0 + 8) * SEQ + col]);
            sacc[nf][0] *= ATT_SCALE / (1.f + __expf(-mv0.x));
            sacc[nf][1] *= ATT_SCALE / (1.f + __expf(-mv0.y));
            sacc[nf][2] *= ATT_SCALE / (1.f + __expf(-mv1.x));
            sacc[nf][3] *= ATT_SCALE / (1.f + __expf(-mv1.y));
            mx0 = fmaxf(mx0, fmaxf(sacc[nf][0], sacc[nf][1]));
            mx1 = fmaxf(mx1, fmaxf(sacc[nf][2], sacc[nf][3]));
        }
        mx0 = fmaxf(mx0, __shfl_xor_sync(0xffffffffu, mx0, 1));
        mx0 = fmaxf(mx0, __shfl_xor_sync(0xffffffffu, mx0, 2));
        mx1 = fmaxf(mx1, __shfl_xor_sync(0xffffffffu, mx1, 1));
        mx1 = fmaxf(mx1, __shfl_xor_sync(0xffffffffu, mx1, 2));

        float mn0 = fmaxf(m0, mx0), mn1 = fmaxf(m1, mx1);
        float sc0 = __expf(m0 - mn0), sc1 = __expf(m1 - mn1);
        m0 = mn0; m1 = mn1;
        l0 *= sc0; l1 *= sc1;
#pragma unroll
        for (int nf = 0; nf < 8; nf++) {
            od[nf][0] *= sc0; od[nf][1] *= sc0;
            od[nf][2] *= sc1; od[nf][3] *= sc1;
        }

        // p = exp(s - m); accumulate l; store P (warp-private rows, no block sync)
        float ls0 = 0.f, ls1 = 0.f;
        float* prow0 = &Ps[(wid * 16 + r) * LDP + 2 * q];
        float* prow1 = prow0 + 8 * LDP;
#pragma unroll
        for (int nf = 0; nf < 8; nf++) {
            float p00 = __expf(sacc[nf][0] - m0);
            float p01 = __expf(sacc[nf][1] - m0);
            float p10 = __expf(sacc[nf][2] - m1);
            float p11 = __expf(sacc[nf][3] - m1);
            ls0 += p00 + p01; ls1 += p10 + p11;
            *reinterpret_cast<float2*>(prow0 + nf * 8) = make_float2(tf32f(p00), tf32f(p01));
            *reinterpret_cast<float2*>(prow1 + nf * 8) = make_float2(tf32f(p10), tf32f(p11));
        }
        l0 += ls0; l1 += ls1;
        __syncwarp();

        // ---- O += P V  (A from Ps rows of this warp, B from Vs) ----
#pragma unroll
        for (int kk = 0; kk < 8; kk++) {
            uint32_t af[4];
            const float* ap = &Ps[(wid * 16 + r) * LDP + kk * 8 + q];
            af[0] = __float_as_uint(ap[0]);
            af[1] = __float_as_uint(ap[8 * LDP]);
            af[2] = __float_as_uint(ap[4]);
            af[3] = __float_as_uint(ap[8 * LDP + 4]);
#pragma unroll
            for (int nf = 0; nf < 8; nf++) {
                uint32_t bf[2];
                const float* bp = &Vs[(nf * 8 + r) * LDP + kk * 8 + q];
                bf[0] = __float_as_uint(bp[0]);
                bf[1] = __float_as_uint(bp[4]);
                mma_tf32(od[nf], af, bf);
            }
        }
        __syncthreads();
    }

    // ---- normalize and write O ----
    l0 += __shfl_xor_sync(0xffffffffu, l0, 1);
    l0 += __shfl_xor_sync(0xffffffffu, l0, 2);
    l1 += __shfl_xor_sync(0xffffffffu, l1, 1);
    l1 += __shfl_xor_sync(0xffffffffu, l1, 2);
    float inv0 = 1.f / l0, inv1 = 1.f / l1;

    size_t orow0 = (size_t)b * SEQ + q0 + wid * 16 + r;
#pragma unroll
    for (int nf = 0; nf < 8; nf++) {
        int col = h * HDIM + nf * 8 + 2 * q;
        *reinterpret_cast<float2*>(&g_O[orow0 * DIMC + col]) =
            make_float2(od[nf][0] * inv0, od[nf][1] * inv0);
        *reinterpret_cast<float2*>(&g_O[(orow0 + 8) * DIMC + col]) =
            make_float2(od[nf][2] * inv1, od[nf][3] * inv1);
    }
}

// ============================================================================
// Kernel 3: out = O @ Wproj^T + bias  (M=8192, N=768, K=768)
// ============================================================================
__global__ __launch_bounds__(256) void proj_tc(const float* __restrict__ w,
                                               const float* __restrict__ bias,
                                               float* __restrict__ out) {
    float acc[4][4][4];
    int brow = blockIdx.y * 128, bcol = blockIdx.x * 128;
    gemm_core<128, 24, 4, 4, 2>(g_O + (size_t)brow * DIMC, DIMC,
                                w + (size_t)bcol * DIMC, DIMC, acc);
    int lane = threadIdx.x & 31, wid = threadIdx.x >> 5;
    int wm = wid % 2, wn = wid / 2, r = lane >> 2, q = lane & 3;

#pragma unroll
    for (int mf = 0; mf < 4; mf++)
#pragma unroll
        for (int nf = 0; nf < 4; nf++) {
            int col = bcol + wn * 32 + nf * 8 + q * 2;
            float2 bb = *reinterpret_cast<const float2*>(&bias[col]);
#pragma unroll
            for (int rr = 0; rr < 2; rr++) {
                int row = brow + wm * 64 + mf * 16 + r + rr * 8;
                float v0 = acc[mf][nf][rr * 2 + 0] + bb.x;
                float v1 = acc[mf][nf][rr * 2 + 1] + bb.y;
                *reinterpret_cast<float2*>(&out[(size_t)row * DIMC + col]) = make_float2(v0, v1);
            }
        }
}

// ============================================================================
extern "C" void kernel_launch(void* const* d_in, const int* in_sizes, int n_in,
                              void* d_out, int out_size) {
    (void)in_sizes; (void)n_in; (void)out_size;
    const float* x        = (const float*)d_in[0];
    const float* w_qkv    = (const float*)d_in[1];
    const float* w_proj   = (const float*)d_in[2];
    const float* b_proj   = (const float*)d_in[3];
    const float* att_mask = (const float*)d_in[4];
    float* out = (float*)d_out;

    const int FLASH_SMEM = (64 * LDP + 64 * LDP + 128 * LDP) * (int)sizeof(float); // 69632
    static int configured = 0;
    cudaFuncSetAttribute(flash_tc, cudaFuncAttributeMaxDynamicSharedMemorySize, FLASH_SMEM);
    (void)configured;

    qkv_tc  <<<dim3(2304 / 128, MROWS / 128), 256>>>(x, w_qkv);
    flash_tc<<<dim3(SEQ / 128, PAIRS), 256, FLASH_SMEM>>>(att_mask);
    proj_tc <<<dim3(DIMC / 128, MROWS / 128), 256>>>(w_proj, b_proj, out);
}

// round 5
// speedup vs baseline: 3.6709x; 1.4506x over previous
#include <cuda_runtime.h>
#include <cstdint>
#include <math.h>

#define DIMC   768
#define NHEADS 12
#define HDIM   64
#define BATCH  8
#define SEQ    1024
#define MROWS  (BATCH*SEQ)
#define PAIRS  (BATCH*NHEADS)
#define ATT_SCALE 0.125f

// ---------------- scratch (static device memory; no cudaMalloc allowed) ----
__device__ __align__(16) float g_Q   [(size_t)PAIRS*SEQ*HDIM];   // tf32-rounded
__device__ __align__(16) float g_K   [(size_t)PAIRS*SEQ*HDIM];   // tf32-rounded
__device__ __align__(16) float g_Vt  [(size_t)PAIRS*HDIM*SEQ];   // tf32-rounded, [pair][d][n]
__device__ __align__(16) float g_O   [(size_t)MROWS*DIMC];       // attn out fp32
__device__ __align__(16) float g_Msig[(size_t)NHEADS*SEQ*SEQ];   // ATT_SCALE*sigmoid(mask)

// ======================= helpers ===========================================
__device__ __forceinline__ uint32_t cvt_tf32(float x) {
    uint32_t r; asm("cvt.rna.tf32.f32 %0, %1;" : "=r"(r) : "f"(x)); return r;
}
__device__ __forceinline__ float tf32f(float x) {
    return __uint_as_float(cvt_tf32(x));
}
__device__ __forceinline__ void mma_tf32(float (&c)[4], const uint32_t (&a)[4],
                                         const uint32_t (&b)[2]) {
    asm volatile("mma.sync.aligned.m16n8k8.row.col.f32.tf32.tf32.f32 "
                 "{%0,%1,%2,%3}, {%4,%5,%6,%7}, {%8,%9}, {%0,%1,%2,%3};"
                 : "+f"(c[0]), "+f"(c[1]), "+f"(c[2]), "+f"(c[3])
                 : "r"(a[0]), "r"(a[1]), "r"(a[2]), "r"(a[3]),
                   "r"(b[0]), "r"(b[1]));
}
__device__ __forceinline__ uint32_t smem_u32(const void* p) {
    uint32_t a;
    asm("{ .reg .u64 t; cvta.to.shared.u64 t, %1; cvt.u32.u64 %0, t; }"
        : "=r"(a) : "l"(p));
    return a;
}
#define CP_ASYNC16(dst, src) \
    asm volatile("cp.async.cg.shared.global [%0], [%1], 16;" \
                 :: "r"(dst), "l"(src) : "memory")
#define CP_COMMIT() asm volatile("cp.async.commit_group;" ::: "memory")
#define CP_WAIT(n)  asm volatile("cp.async.wait_group %0;" :: "n"(n) : "memory")

// ============================================================================
// NT GEMM core (R3 proven): C[128 x BN] = A[128 x K] * B[BN x K]^T
// ============================================================================
template <int BN, int NC, int MF, int NF, int WMDIV>
__device__ __forceinline__ void gemm_core(const float* __restrict__ A, int lda,
                                          const float* __restrict__ B, int ldb,
                                          float (&acc)[MF][NF][4]) {
    constexpr int LDK   = 36;
    constexpr int APASS = 4;
    constexpr int BPASS = BN / 32;
    __shared__ float As[128 * LDK];
    __shared__ float Bs[BN * LDK];

    const int tid  = threadIdx.x;
    const int lane = tid & 31;
    const int wid  = tid >> 5;
    const int wm   = wid % WMDIV;
    const int wn   = wid / WMDIV;
    const int mrow0 = wm * (MF * 16);
    const int ncol0 = wn * (NF * 8);
    const int r = lane >> 2, q = lane & 3;

#pragma unroll
    for (int mf = 0; mf < MF; mf++)
#pragma unroll
        for (int nf = 0; nf < NF; nf++)
#pragma unroll
            for (int i = 0; i < 4; i++) acc[mf][nf][i] = 0.f;

    float4 ar[APASS], br[BPASS];
#pragma unroll
    for (int p = 0; p < APASS; p++) {
        int idx = tid + p * 256;
        ar[p] = *reinterpret_cast<const float4*>(A + (size_t)(idx >> 3) * lda + (idx & 7) * 4);
    }
#pragma unroll
    for (int p = 0; p < BPASS; p++) {
        int idx = tid + p * 256;
        br[p] = *reinterpret_cast<const float4*>(B + (size_t)(idx >> 3) * ldb + (idx & 7) * 4);
    }

#pragma unroll 1
    for (int i = 0; i < NC; i++) {
#pragma unroll
        for (int p = 0; p < APASS; p++) {
            int idx = tid + p * 256;
            uint32_t* d = reinterpret_cast<uint32_t*>(&As[(idx >> 3) * LDK + (idx & 7) * 4]);
            d[0] = cvt_tf32(ar[p].x); d[1] = cvt_tf32(ar[p].y);
            d[2] = cvt_tf32(ar[p].z); d[3] = cvt_tf32(ar[p].w);
        }
#pragma unroll
        for (int p = 0; p < BPASS; p++) {
            int idx = tid + p * 256;
            uint32_t* d = reinterpret_cast<uint32_t*>(&Bs[(idx >> 3) * LDK + (idx & 7) * 4]);
            d[0] = cvt_tf32(br[p].x); d[1] = cvt_tf32(br[p].y);
            d[2] = cvt_tf32(br[p].z); d[3] = cvt_tf32(br[p].w);
        }
        __syncthreads();

        if (i + 1 < NC) {
            int k0 = (i + 1) * 32;
#pragma unroll
            for (int p = 0; p < APASS; p++) {
                int idx = tid + p * 256;
                ar[p] = *reinterpret_cast<const float4*>(A + (size_t)(idx >> 3) * lda + k0 + (idx & 7) * 4);
            }
#pragma unroll
            for (int p = 0; p < BPASS; p++) {
                int idx = tid + p * 256;
                br[p] = *reinterpret_cast<const float4*>(B + (size_t)(idx >> 3) * ldb + k0 + (idx & 7) * 4);
            }
        }

#pragma unroll
        for (int kk = 0; kk < 32; kk += 8) {
            uint32_t af[MF][4], bf[NF][2];
#pragma unroll
            for (int mf = 0; mf < MF; mf++) {
                const float* ap = &As[(mrow0 + mf * 16 + r) * LDK + kk + q];
                af[mf][0] = __float_as_uint(ap[0]);
                af[mf][1] = __float_as_uint(ap[8 * LDK]);
                af[mf][2] = __float_as_uint(ap[4]);
                af[mf][3] = __float_as_uint(ap[8 * LDK + 4]);
            }
#pragma unroll
            for (int nf = 0; nf < NF; nf++) {
                const float* bp = &Bs[(ncol0 + nf * 8 + r) * LDK + kk + q];
                bf[nf][0] = __float_as_uint(bp[0]);
                bf[nf][1] = __float_as_uint(bp[4]);
            }
#pragma unroll
            for (int mf = 0; mf < MF; mf++)
#pragma unroll
                for (int nf = 0; nf < NF; nf++)
                    mma_tf32(acc[mf][nf], af[mf], bf[nf]);
        }
        __syncthreads();
    }
}

// ============================================================================
// Kernel 0: precompute ATT_SCALE * sigmoid(att_mask)  (12M elements)
// ============================================================================
__global__ __launch_bounds__(256) void presig(const float* __restrict__ m) {
    size_t i = ((size_t)blockIdx.x * 256 + threadIdx.x) * 4;
    float4 v = *reinterpret_cast<const float4*>(m + i);
    float4 o;
    o.x = ATT_SCALE / (1.f + __expf(-v.x));
    o.y = ATT_SCALE / (1.f + __expf(-v.y));
    o.z = ATT_SCALE / (1.f + __expf(-v.z));
    o.w = ATT_SCALE / (1.f + __expf(-v.w));
    *reinterpret_cast<float4*>(g_Msig + i) = o;
}

// ============================================================================
// Kernel 1: QKV projection + scatter to Q/K/Vt (stored tf32-rounded)
// ============================================================================
__global__ __launch_bounds__(256) void qkv_tc(const float* __restrict__ x,
                                              const float* __restrict__ w) {
    float acc[4][4][4];
    int brow = blockIdx.y * 128, bcol = blockIdx.x * 128;
    gemm_core<128, 24, 4, 4, 2>(x + (size_t)brow * DIMC, DIMC,
                                w + (size_t)bcol * DIMC, DIMC, acc);
    int lane = threadIdx.x & 31, wid = threadIdx.x >> 5;
    int wm = wid % 2, wn = wid / 2, r = lane >> 2, q = lane & 3;
    int part = bcol / 768, rem0 = bcol - part * 768;

#pragma unroll
    for (int mf = 0; mf < 4; mf++)
#pragma unroll
        for (int nf = 0; nf < 4; nf++) {
            int col = rem0 + wn * 32 + nf * 8 + q * 2;
            int h = col >> 6, d = col & 63;
#pragma unroll
            for (int rr = 0; rr < 2; rr++) {
                int m = brow + wm * 64 + mf * 16 + r + rr * 8;
                int b = m >> 10, nq = m & 1023;
                float v0 = tf32f(acc[mf][nf][rr * 2 + 0]);
                float v1 = tf32f(acc[mf][nf][rr * 2 + 1]);
                if (part < 2) {
                    float* dst = (part == 0) ? g_Q : g_K;
                    *reinterpret_cast<float2*>(
                        &dst[(((size_t)(b * NHEADS + h)) * SEQ + nq) * HDIM + d]) =
                        make_float2(v0, v1);
                } else {
                    size_t pb = ((size_t)(b * NHEADS + h)) * HDIM;
                    g_Vt[(pb + d)     * SEQ + nq] = v0;
                    g_Vt[(pb + d + 1) * SEQ + nq] = v1;
                }
            }
        }
}

// ============================================================================
// Kernel 2: FUSED flash attention, cp.async double-buffered K/V tiles.
// 256 threads = 8 warps; warp w owns q-rows [16w,16w+16). KT=64, 16 iters.
// ============================================================================
#define KT 64
#define LDP 68
#define NITER (SEQ / KT)

__global__ __launch_bounds__(256) void flash_tc() {
    extern __shared__ float sm[];
    // [buf0: K(64*LDP) V(64*LDP)][buf1: K V][Ps: 128*LDP]
    float* Ps = sm + 4 * 64 * LDP;

    const int tid = threadIdx.x, lane = tid & 31, wid = tid >> 5;
    const int r = lane >> 2, q = lane & 3;
    const int pair = blockIdx.y;
    const int h = pair % NHEADS, b = pair / NHEADS;
    const int q0 = blockIdx.x * 128;

    const float* Qg = g_Q  + (size_t)pair * SEQ * HDIM + (size_t)q0 * HDIM;
    const float* Kg = g_K  + (size_t)pair * SEQ * HDIM;
    const float* Vg = g_Vt + (size_t)pair * HDIM * SEQ;
    const float* Mg = g_Msig + (size_t)h * SEQ * SEQ;

    auto copyKV = [&](int kb, int buf) {
        float* Kd = sm + buf * (2 * 64 * LDP);
        float* Vd = Kd + 64 * LDP;
        const float* Ksrc = Kg + (size_t)kb * KT * HDIM;
        const float* Vsrc = Vg + kb * KT;
#pragma unroll
        for (int p = 0; p < 4; p++) {
            int idx = tid + p * 256;
            int row = idx >> 4, c = idx & 15;
            CP_ASYNC16(smem_u32(&Kd[row * LDP + c * 4]), Ksrc + (size_t)row * HDIM + c * 4);
            CP_ASYNC16(smem_u32(&Vd[row * LDP + c * 4]), Vsrc + (size_t)row * SEQ + c * 4);
        }
    };

    // ---- prologue: Q tile + stage 0, then stage 1 ----
#pragma unroll
    for (int p = 0; p < 8; p++) {
        int idx = tid + p * 256;
        int row = idx >> 4, c = idx & 15;
        CP_ASYNC16(smem_u32(&Ps[row * LDP + c * 4]), Qg + (size_t)row * HDIM + c * 4);
    }
    copyKV(0, 0);
    CP_COMMIT();
    copyKV(1, 1);
    CP_COMMIT();
    CP_WAIT(1);           // Q + stage0 ready
    __syncthreads();

    // ---- Q fragments in registers ----
    uint32_t qa[8][4];
#pragma unroll
    for (int kk = 0; kk < 8; kk++) {
        const float* ap = &Ps[(wid * 16 + r) * LDP + kk * 8 + q];
        qa[kk][0] = __float_as_uint(ap[0]);
        qa[kk][1] = __float_as_uint(ap[8 * LDP]);
        qa[kk][2] = __float_as_uint(ap[4]);
        qa[kk][3] = __float_as_uint(ap[8 * LDP + 4]);
    }
    __syncthreads();

    float od[8][4];
#pragma unroll
    for (int nf = 0; nf < 8; nf++)
#pragma unroll
        for (int i = 0; i < 4; i++) od[nf][i] = 0.f;
    float m0 = -1e30f, m1 = -1e30f, l0 = 0.f, l1 = 0.f;

    const int row_s0 = q0 + wid * 16 + r;

#pragma unroll 1
    for (int kb = 0; kb < NITER; kb++) {
        const int buf = kb & 1;
        const float* Ks = sm + buf * (2 * 64 * LDP);
        const float* Vs = Ks + 64 * LDP;

        // ---- S = Q K^T ----
        float sacc[8][4];
#pragma unroll
        for (int nf = 0; nf < 8; nf++)
#pragma unroll
            for (int i = 0; i < 4; i++) sacc[nf][i] = 0.f;
#pragma unroll
        for (int kk = 0; kk < 8; kk++) {
#pragma unroll
            for (int nf = 0; nf < 8; nf++) {
                uint32_t bf[2];
                const float* bp = &Ks[(nf * 8 + r) * LDP + kk * 8 + q];
                bf[0] = __float_as_uint(bp[0]);
                bf[1] = __float_as_uint(bp[4]);
                mma_tf32(sacc[nf], qa[kk], bf);
            }
        }

        // ---- apply precomputed scale*sigmoid(mask), online softmax ----
        float mx0 = -1e30f, mx1 = -1e30f;
#pragma unroll
        for (int nf = 0; nf < 8; nf++) {
            int col = kb * KT + nf * 8 + 2 * q;
            float2 g0 = *reinterpret_cast<const float2*>(&Mg[(size_t)row_s0 * SEQ + col]);
            float2 g1 = *reinterpret_cast<const float2*>(&Mg[(size_t)(row_s0 + 8) * SEQ + col]);
            sacc[nf][0] *= g0.x;
            sacc[nf][1] *= g0.y;
            sacc[nf][2] *= g1.x;
            sacc[nf][3] *= g1.y;
            mx0 = fmaxf(mx0, fmaxf(sacc[nf][0], sacc[nf][1]));
            mx1 = fmaxf(mx1, fmaxf(sacc[nf][2], sacc[nf][3]));
        }
        mx0 = fmaxf(mx0, __shfl_xor_sync(0xffffffffu, mx0, 1));
        mx0 = fmaxf(mx0, __shfl_xor_sync(0xffffffffu, mx0, 2));
        mx1 = fmaxf(mx1, __shfl_xor_sync(0xffffffffu, mx1, 1));
        mx1 = fmaxf(mx1, __shfl_xor_sync(0xffffffffu, mx1, 2));

        float mn0 = fmaxf(m0, mx0), mn1 = fmaxf(m1, mx1);
        float sc0 = __expf(m0 - mn0), sc1 = __expf(m1 - mn1);
        m0 = mn0; m1 = mn1;
        l0 *= sc0; l1 *= sc1;
#pragma unroll
        for (int nf = 0; nf < 8; nf++) {
            od[nf][0] *= sc0; od[nf][1] *= sc0;
            od[nf][2] *= sc1; od[nf][3] *= sc1;
        }

        // p = exp(s - m); store P (warp-private rows)
        float ls0 = 0.f, ls1 = 0.f;
        float* prow0 = &Ps[(wid * 16 + r) * LDP + 2 * q];
        float* prow1 = prow0 + 8 * LDP;
#pragma unroll
        for (int nf = 0; nf < 8; nf++) {
            float p00 = __expf(sacc[nf][0] - m0);
            float p01 = __expf(sacc[nf][1] - m0);
            float p10 = __expf(sacc[nf][2] - m1);
            float p11 = __expf(sacc[nf][3] - m1);
            ls0 += p00 + p01; ls1 += p10 + p11;
            *reinterpret_cast<float2*>(prow0 + nf * 8) = make_float2(tf32f(p00), tf32f(p01));
            *reinterpret_cast<float2*>(prow1 + nf * 8) = make_float2(tf32f(p10), tf32f(p11));
        }
        l0 += ls0; l1 += ls1;
        __syncwarp();

        // ---- O += P V ----
#pragma unroll
        for (int kk = 0; kk < 8; kk++) {
            uint32_t af[4];
            const float* ap = &Ps[(wid * 16 + r) * LDP + kk * 8 + q];
            af[0] = __float_as_uint(ap[0]);
            af[1] = __float_as_uint(ap[8 * LDP]);
            af[2] = __float_as_uint(ap[4]);
            af[3] = __float_as_uint(ap[8 * LDP + 4]);
#pragma unroll
            for (int nf = 0; nf < 8; nf++) {
                uint32_t bf[2];
                const float* bp = &Vs[(nf * 8 + r) * LDP + kk * 8 + q];
                bf[0] = __float_as_uint(bp[0]);
                bf[1] = __float_as_uint(bp[4]);
                mma_tf32(od[nf], af, bf);
            }
        }

        if (kb == NITER - 1) break;
        __syncthreads();                       // all warps done with buf
        if (kb + 2 < NITER) {
            copyKV(kb + 2, buf);               // refill the buffer just freed
            CP_COMMIT();
            CP_WAIT(1);                        // stage kb+1 complete
        } else {
            CP_WAIT(0);
        }
        __syncthreads();                       // next buf visible to all warps
    }

    // ---- normalize and write O ----
    l0 += __shfl_xor_sync(0xffffffffu, l0, 1);
    l0 += __shfl_xor_sync(0xffffffffu, l0, 2);
    l1 += __shfl_xor_sync(0xffffffffu, l1, 1);
    l1 += __shfl_xor_sync(0xffffffffu, l1, 2);
    float inv0 = 1.f / l0, inv1 = 1.f / l1;

    size_t orow0 = (size_t)b * SEQ + q0 + wid * 16 + r;
#pragma unroll
    for (int nf = 0; nf < 8; nf++) {
        int col = h * HDIM + nf * 8 + 2 * q;
        *reinterpret_cast<float2*>(&g_O[orow0 * DIMC + col]) =
            make_float2(od[nf][0] * inv0, od[nf][1] * inv0);
        *reinterpret_cast<float2*>(&g_O[(orow0 + 8) * DIMC + col]) =
            make_float2(od[nf][2] * inv1, od[nf][3] * inv1);
    }
}

// ============================================================================
// Kernel 3: out = O @ Wproj^T + bias
// ============================================================================
__global__ __launch_bounds__(256) void proj_tc(const float* __restrict__ w,
                                               const float* __restrict__ bias,
                                               float* __restrict__ out) {
    float acc[4][4][4];
    int brow = blockIdx.y * 128, bcol = blockIdx.x * 128;
    gemm_core<128, 24, 4, 4, 2>(g_O + (size_t)brow * DIMC, DIMC,
                                w + (size_t)bcol * DIMC, DIMC, acc);
    int lane = threadIdx.x & 31, wid = threadIdx.x >> 5;
    int wm = wid % 2, wn = wid / 2, r = lane >> 2, q = lane & 3;

#pragma unroll
    for (int mf = 0; mf < 4; mf++)
#pragma unroll
        for (int nf = 0; nf < 4; nf++) {
            int col = bcol + wn * 32 + nf * 8 + q * 2;
            float2 bb = *reinterpret_cast<const float2*>(&bias[col]);
#pragma unroll
            for (int rr = 0; rr < 2; rr++) {
                int row = brow + wm * 64 + mf * 16 + r + rr * 8;
                float v0 = acc[mf][nf][rr * 2 + 0] + bb.x;
                float v1 = acc[mf][nf][rr * 2 + 1] + bb.y;
                *reinterpret_cast<float2*>(&out[(size_t)row * DIMC + col]) = make_float2(v0, v1);
            }
        }
}

// ============================================================================
extern "C" void kernel_launch(void* const* d_in, const int* in_sizes, int n_in,
                              void* d_out, int out_size) {
    (void)in_sizes; (void)n_in; (void)out_size;
    const float* x        = (const float*)d_in[0];
    const float* w_qkv    = (const float*)d_in[1];
    const float* w_proj   = (const float*)d_in[2];
    const float* b_proj   = (const float*)d_in[3];
    const float* att_mask = (const float*)d_in[4];
    float* out = (float*)d_out;

    const int FLASH_SMEM = (4 * 64 * LDP + 128 * LDP) * (int)sizeof(float); // 104448
    cudaFuncSetAttribute(flash_tc, cudaFuncAttributeMaxDynamicSharedMemorySize, FLASH_SMEM);

    presig  <<<(NHEADS * SEQ * SEQ) / (256 * 4), 256>>>(att_mask);
    qkv_tc  <<<dim3(2304 / 128, MROWS / 128), 256>>>(x, w_qkv);
    flash_tc<<<dim3(SEQ / 128, PAIRS), 256, FLASH_SMEM>>>();
    proj_tc <<<dim3(DIMC / 128, MROWS / 128), 256>>>(w_proj, b_proj, out);
}